// round 8
// baseline (speedup 1.0000x reference)
#include <cuda_runtime.h>
#include <cuda_bf16.h>
#include <math.h>
#include <stdint.h>

// Problem constants (reference: N=1024, L=30, G=10000, NB=64)
#define LDIM    30
#define GPB     128          // genes per block tile (= THREADS, 1 gene/thread)
#define THREADS 128
#define MAXC    128          // max cells per batch (mean 16; binomial tail >>12 sigma)
#define NCPAD   128          // zsT row stride (floats), 16B-aligned groups

typedef unsigned long long u64;

// packed f32x2 helpers (sm_103a FFMA2 only reachable via PTX)
#define FFMA2(d, a, b, c) \
    asm("fma.rn.f32x2 %0, %1, %2, %3;" : "=l"(d) : "l"(a), "l"(b), "l"(c))
#define PACK2(d, x) \
    asm("mov.b64 %0, {%1, %2};" : "=l"(d) : "f"(x), "f"(x))
#define UNPACK2(lo, hi, v) \
    asm("mov.b64 {%0, %1}, %2;" : "=f"(lo), "=f"(hi) : "l"(v))

__device__ __forceinline__ float softplus_fast(float x) {
    // max(x,0) + log1p(exp(-|x|)); fast intrinsics (rel err ~1e-6 << 1e-3 budget)
    return fmaxf(x, 0.0f) + __logf(1.0f + __expf(-fabsf(x)));
}

__device__ __forceinline__ void cp_async16(unsigned int saddr, const void* gptr) {
    asm volatile("cp.async.cg.shared.global [%0], [%1], 16;\n" :: "r"(saddr), "l"(gptr));
}
__device__ __forceinline__ void cp_commit() { asm volatile("cp.async.commit_group;\n" ::: "memory"); }
__device__ __forceinline__ void cp_wait0()  { asm volatile("cp.async.wait_group 0;\n" ::: "memory"); }

// ---------------------------------------------------------------------------
// grid = (ceil(G/GPB), NB + 1), block = 128.
//   y <  NB : decoder for batch y over a 128-gene tile.
//             z staged TRANSPOSED (zsT[l][cell]) so cell-pairs pack into
//             f32x2 lanes -> inner loop is LDS.128 + FFMA2 (2 MACs/inst).
//   y == NB : inverse_dispersion = exp(px_r)
// ---------------------------------------------------------------------------
__global__ __launch_bounds__(THREADS, 5) void fused_decoder_kernel(
    const float* __restrict__ z,      // [N, L]
    const int*   __restrict__ bc,     // [N]
    const float* __restrict__ sf,     // [N, 1]
    const float* __restrict__ W,      // [L, G]
    const float* __restrict__ A,      // [NB, G, L]
    const float* __restrict__ bemb,   // [NB, G]
    const float* __restrict__ px_r,   // [G]
    float* __restrict__ out,          // [N, G] ++ [G]
    int N, int G, int NB)
{
    // ---- exp(px_r) slice ----
    if (blockIdx.y == (unsigned)NB) {
        float* od = out + (size_t)N * G;
        for (int g = blockIdx.x * THREADS + threadIdx.x; g < G; g += gridDim.x * THREADS)
            od[g] = __expf(px_r[g]);
        return;
    }

    __shared__ float as[GPB * LDIM];        // 15 KB  A tile (cp.async staged)
    __shared__ float zsT[LDIM * NCPAD];     // 15 KB  transposed z: zsT[l*NCPAD + cell]
    __shared__ int   cells[MAXC];
    __shared__ float sfs[MAXC];
    __shared__ int   scount;

    const int tid   = threadIdx.x;
    const int b     = blockIdx.y;
    const int gbase = blockIdx.x * GPB;
    const int nst   = min(GPB, G - gbase);

    // ---- kick off A tile load first (hide behind compaction/staging) ----
    {
        const float*  srcf = A + ((size_t)b * G + gbase) * LDIM;
        unsigned int  dst  = (unsigned int)__cvta_generic_to_shared(&as[0]);
        const int w4 = (nst * LDIM) >> 2;               // nst*30 divisible by 4 here
        const float4* src4 = (const float4*)srcf;
        for (int i = tid; i < w4; i += THREADS) cp_async16(dst + i * 16, src4 + i);
    }
    cp_commit();

    // ---- compact this batch's cell list (bc: 4 KB, L2-hot) ----
    if (tid == 0) scount = 0;
    __syncthreads();
    for (int n = tid; n < N; n += THREADS) {
        if (bc[n] == b) {
            int p = atomicAdd(&scount, 1);
            if (p < MAXC) cells[p] = n;
        }
    }
    __syncthreads();
    const int ncell = min(scount, MAXC);
    if (ncell == 0) return;                 // uniform across block
    const int ncp = (ncell + 7) & ~7;       // padded to 8-cell groups

    // ---- stage z transposed: thread t handles cell t (few active, one-shot) ----
    if (tid < ncell) {
        const int cell = cells[tid];
        const float* zr = z + (size_t)cell * LDIM;
        #pragma unroll
        for (int l = 0; l < LDIM; l++)
            zsT[l * NCPAD + tid] = zr[l];   // same-l threads -> consecutive banks
        sfs[tid] = sf[cell];
    } else if (tid < ncp) {
        #pragma unroll
        for (int l = 0; l < LDIM; l++)
            zsT[l * NCPAD + tid] = 0.0f;    // zero tail so packed math stays finite
    }
    cp_wait0();
    __syncthreads();                         // as[] + zsT + cells/sfs visible

    // ---- per-thread packed coefficients c2[l] = {c,c}, c = W[l,g]+A[b,g,l] ----
    const int  g   = gbase + tid;
    const bool act = (tid < nst);
    u64 c2[LDIM];
    u64 bias2 = 0;
    if (act) {
        #pragma unroll
        for (int l = 0; l < LDIM; l++) {
            float cv = W[(size_t)l * G + g] + as[tid * LDIM + l];
            PACK2(c2[l], cv);
        }
        float bv = bemb[(size_t)b * G + g];
        PACK2(bias2, bv);
    }

    if (act) {
        for (int c0 = 0; c0 < ncp; c0 += 8) {
            const float* col = zsT + c0;
            u64 a0 = bias2, a1 = bias2, a2 = bias2, a3 = bias2;
            #pragma unroll
            for (int l = 0; l < LDIM; l++) {
                // 8 cells' z[l]: two LDS.128 broadcasts
                ulonglong2 v0 = *(const ulonglong2*)(col + l * NCPAD);
                ulonglong2 v1 = *(const ulonglong2*)(col + l * NCPAD + 4);
                FFMA2(a0, c2[l], v0.x, a0);     // cells c0+0, c0+1
                FFMA2(a1, c2[l], v0.y, a1);     // cells c0+2, c0+3
                FFMA2(a2, c2[l], v1.x, a2);     // cells c0+4, c0+5
                FFMA2(a3, c2[l], v1.y, a3);     // cells c0+6, c0+7
            }
            // epilogue: unpack, softplus, scale, coalesced scalar stores
            float v[8];
            UNPACK2(v[0], v[1], a0);
            UNPACK2(v[2], v[3], a1);
            UNPACK2(v[4], v[5], a2);
            UNPACK2(v[6], v[7], a3);
            const int nrem = min(8, ncell - c0);
            #pragma unroll
            for (int k = 0; k < 8; k++) {
                if (k < nrem)
                    out[(size_t)cells[c0 + k] * G + g] =
                        softplus_fast(v[k]) * sfs[c0 + k];
            }
        }
    }
}

// ---------------------------------------------------------------------------
// Inputs (metadata order): z, batch_covariate, size_factor, W_amat, A_emb,
//                          b_emb, px_r.  Output: mean [N,G] ++ inv_disp [G].
// ---------------------------------------------------------------------------
extern "C" void kernel_launch(void* const* d_in, const int* in_sizes, int n_in,
                              void* d_out, int out_size) {
    const float* z    = (const float*)d_in[0];
    const int*   bc   = (const int*)  d_in[1];
    const float* sf   = (const float*)d_in[2];
    const float* W    = (const float*)d_in[3];
    const float* A    = (const float*)d_in[4];
    const float* bemb = (const float*)d_in[5];
    const float* px_r = (const float*)d_in[6];
    float* out = (float*)d_out;

    const int N  = in_sizes[1];        // 1024
    const int G  = in_sizes[6];        // 10000
    const int NB = in_sizes[5] / G;    // 64

    dim3 grid((G + GPB - 1) / GPB, NB + 1);
    fused_decoder_kernel<<<grid, THREADS>>>(z, bc, sf, W, A, bemb, px_r, out, N, G, NB);
}

// round 10
// speedup vs baseline: 1.0184x; 1.0184x over previous
#include <cuda_runtime.h>
#include <cuda_bf16.h>
#include <math.h>
#include <stdint.h>

// Problem constants (reference: N=1024, L=30, G=10000, NB=64)
#define LDIM    30
#define ZROW    32           // padded z row (2 zero pads) -> LDS.128 inner loop
#define GPB     128          // genes per block tile (= THREADS, 1 gene/thread)
#define THREADS 128
#define CHUNK   64           // cells staged per z chunk (covers ncell~16 in one pass)
#define NMAX    1024

__device__ __forceinline__ float softplus_fast(float x) {
    // max(x,0) + log1p(exp(-|x|)); fast intrinsics (rel err ~1e-6 << 1e-3 budget)
    return fmaxf(x, 0.0f) + __logf(1.0f + __expf(-fabsf(x)));
}

__device__ __forceinline__ void cp_async16(unsigned int saddr, const void* gptr) {
    asm volatile("cp.async.cg.shared.global [%0], [%1], 16;\n" :: "r"(saddr), "l"(gptr));
}
__device__ __forceinline__ void cp_commit() { asm volatile("cp.async.commit_group;\n" ::: "memory"); }
__device__ __forceinline__ void cp_wait0()  { asm volatile("cp.async.wait_group 0;\n" ::: "memory"); }

// ---------------------------------------------------------------------------
// grid = (ceil(G/GPB), NB + 1), block = 128 threads.
//   y <  NB : decoder for batch y over a 128-gene tile
//   y == NB : inverse_dispersion = exp(px_r)
// Inner loop: 4 cells/iter, 4 independent FMA chains, no predication
// (cell list padded by duplicating the last cell; duplicate stores benign).
// ---------------------------------------------------------------------------
__global__ __launch_bounds__(THREADS, 7) void fused_decoder_kernel(
    const float* __restrict__ z,      // [N, L]
    const int*   __restrict__ bc,     // [N]
    const float* __restrict__ sf,     // [N, 1]
    const float* __restrict__ W,      // [L, G]
    const float* __restrict__ A,      // [NB, G, L]
    const float* __restrict__ bemb,   // [NB, G]
    const float* __restrict__ px_r,   // [G]
    float* __restrict__ out,          // [N, G] ++ [G]
    int N, int G, int NB)
{
    // ---- exp(px_r) slice ----
    if (blockIdx.y == (unsigned)NB) {
        float* od = out + (size_t)N * G;
        for (int g = blockIdx.x * THREADS + threadIdx.x; g < G; g += gridDim.x * THREADS)
            od[g] = __expf(px_r[g]);
        return;
    }

    __shared__ float as[GPB * LDIM];        // 15 KB  A tile (cp.async staged)
    __shared__ float zs[CHUNK * ZROW];      //  8 KB  z chunk, padded rows
    __shared__ int   cells[NMAX + 4];       //  4 KB  cell list (padded to mult of 4)
    __shared__ float sfs[CHUNK];
    __shared__ int   scount;

    const int tid   = threadIdx.x;
    const int b     = blockIdx.y;
    const int gbase = blockIdx.x * GPB;
    const int nst   = min(GPB, G - gbase);

    // ---- kick off A tile load first (hide behind compaction) ----
    {
        const float*  srcf = A + ((size_t)b * G + gbase) * LDIM;
        unsigned int  dst  = (unsigned int)__cvta_generic_to_shared(&as[0]);
        const int w4 = (nst * LDIM) >> 2;            // nst*30 divisible by 4 here
        const float4* src4 = (const float4*)srcf;
        for (int i = tid; i < w4; i += THREADS) cp_async16(dst + i * 16, src4 + i);
    }
    cp_commit();

    // ---- compact this batch's cell list (bc: 4 KB, L2-hot) ----
    if (tid == 0) scount = 0;
    __syncthreads();
    for (int n = tid; n < N; n += THREADS) {
        if (bc[n] == b) {
            int p = atomicAdd(&scount, 1);
            cells[p] = n;
        }
    }
    cp_wait0();
    __syncthreads();                       // cells/scount + as[] visible everywhere
    const int ncell = scount;
    if (ncell == 0) return;                // uniform across block
    const int ncp = (ncell + 3) & ~3;      // pad to multiple of 4
    if (tid < ncp - ncell) cells[ncell + tid] = cells[ncell - 1];  // duplicate last

    // ---- per-thread combined coefficients c[l] = W[l,g] + A[b,g,l] ----
    const int  g   = gbase + tid;
    const bool act = (tid < nst);
    float c[ZROW];
    float bias = 0.0f;
    if (act) {
        #pragma unroll
        for (int l = 0; l < LDIM; l++)
            c[l] = W[(size_t)l * G + g] + as[tid * LDIM + l];   // W coalesced, L2-hot
        c[30] = 0.0f; c[31] = 0.0f;
        bias = bemb[(size_t)b * G + g];
    }
    __syncthreads();                        // padding writes visible before staging

    for (int cc = 0; cc < ncp; cc += CHUNK) {
        const int nc = min(CHUNK, ncp - cc);        // multiple of 4 (CHUNK mult of 4)
        __syncthreads();                    // previous chunk's zs reads complete
        // stage z rows (padded to 32, zero pads) + size factors
        for (int i = tid; i < nc * (LDIM / 2); i += THREADS) {
            int ci = i / (LDIM / 2), l = i - ci * (LDIM / 2);
            float2 v = *(const float2*)(z + (size_t)cells[cc + ci] * LDIM + 2 * l);
            *(float2*)(zs + ci * ZROW + 2 * l) = v;
        }
        for (int i = tid; i < nc; i += THREADS) {
            zs[i * ZROW + 30] = 0.0f;
            zs[i * ZROW + 31] = 0.0f;
            sfs[i] = sf[cells[cc + i]];
        }
        __syncthreads();

        if (act) {
            for (int i = 0; i < nc; i += 4) {
                const float4* z0 = (const float4*)(zs + (i    ) * ZROW);
                const float4* z1 = (const float4*)(zs + (i + 1) * ZROW);
                const float4* z2 = (const float4*)(zs + (i + 2) * ZROW);
                const float4* z3 = (const float4*)(zs + (i + 3) * ZROW);
                float a0 = bias, a1 = bias, a2 = bias, a3 = bias;
                #pragma unroll
                for (int q = 0; q < ZROW / 4; q++) {
                    float4 v0 = z0[q];                 // broadcast LDS.128
                    a0 = fmaf(c[4*q+0], v0.x, a0);
                    a0 = fmaf(c[4*q+1], v0.y, a0);
                    a0 = fmaf(c[4*q+2], v0.z, a0);
                    a0 = fmaf(c[4*q+3], v0.w, a0);
                    float4 v1 = z1[q];
                    a1 = fmaf(c[4*q+0], v1.x, a1);
                    a1 = fmaf(c[4*q+1], v1.y, a1);
                    a1 = fmaf(c[4*q+2], v1.z, a1);
                    a1 = fmaf(c[4*q+3], v1.w, a1);
                    float4 v2 = z2[q];
                    a2 = fmaf(c[4*q+0], v2.x, a2);
                    a2 = fmaf(c[4*q+1], v2.y, a2);
                    a2 = fmaf(c[4*q+2], v2.z, a2);
                    a2 = fmaf(c[4*q+3], v2.w, a2);
                    float4 v3 = z3[q];
                    a3 = fmaf(c[4*q+0], v3.x, a3);
                    a3 = fmaf(c[4*q+1], v3.y, a3);
                    a3 = fmaf(c[4*q+2], v3.z, a3);
                    a3 = fmaf(c[4*q+3], v3.w, a3);
                }
                // duplicate-padded cells store the same value twice: benign
                out[(size_t)cells[cc + i    ] * G + g] = softplus_fast(a0) * sfs[i    ];
                out[(size_t)cells[cc + i + 1] * G + g] = softplus_fast(a1) * sfs[i + 1];
                out[(size_t)cells[cc + i + 2] * G + g] = softplus_fast(a2) * sfs[i + 2];
                out[(size_t)cells[cc + i + 3] * G + g] = softplus_fast(a3) * sfs[i + 3];
            }
        }
    }
}

// ---------------------------------------------------------------------------
// Inputs (metadata order): z, batch_covariate, size_factor, W_amat, A_emb,
//                          b_emb, px_r.  Output: mean [N,G] ++ inv_disp [G].
// ---------------------------------------------------------------------------
extern "C" void kernel_launch(void* const* d_in, const int* in_sizes, int n_in,
                              void* d_out, int out_size) {
    const float* z    = (const float*)d_in[0];
    const int*   bc   = (const int*)  d_in[1];
    const float* sf   = (const float*)d_in[2];
    const float* W    = (const float*)d_in[3];
    const float* A    = (const float*)d_in[4];
    const float* bemb = (const float*)d_in[5];
    const float* px_r = (const float*)d_in[6];
    float* out = (float*)d_out;

    const int N  = in_sizes[1];        // 1024
    const int G  = in_sizes[6];        // 10000
    const int NB = in_sizes[5] / G;    // 64

    dim3 grid((G + GPB - 1) / GPB, NB + 1);
    fused_decoder_kernel<<<grid, THREADS>>>(z, bc, sf, W, A, bemb, px_r, out, N, G, NB);
}